// round 11
// baseline (speedup 1.0000x reference)
#include <cuda_runtime.h>
#include <math.h>

#define BB   16
#define TT   1024
#define NN   128
#define NW   498
#define DM   256
#define IND  384
#define NCH  8       // window chunks (64 windows each, last=50)
#define CHW  64
#define MCH  24      // window chunks for musig
#define MCW  21

// ---------------- scratch (static device globals; no allocation) ----------------
__device__ float g_mu  [BB*NW*NN];          // per (b,w,n) window mean
__device__ float g_rstd[BB*NW*NN];          // per (b,w,n) 1/std
__device__ float g_S   [8*NCH*BB*NN*NN];    // per-chunk partial power sums S1..S8 (later reused for ho planes)
__device__ float g_cm  [3*BB*NN*NN];        // central moments d=2,4,8 (full, diag=0)
__device__ float g_rmean[3*BB*NN];
__device__ float g_rinv [3*BB*NN];
__device__ float g_A  [BB*NN*NN];           // averaged ho (diag=1)
__device__ float g_dis[BB*NN];              // rsqrt(rowsum(A)+1)
__device__ float g_X  [BB*NN*IND];          // layernormed features
__device__ float g_P  [BB*NN*DM];
__device__ float g_H  [BB*NN*DM];
__device__ float g_P2 [BB*NN*DM];
__device__ float g_H2 [BB*NN*DM];

__device__ const int c_ti[10] = {0,0,0,0,1,1,1,2,2,3};
__device__ const int c_tj[10] = {0,1,2,3,1,2,3,2,3,3};

#define LD4(p) (*reinterpret_cast<const float4*>(p))
#define LDU(p) (*reinterpret_cast<const unsigned long long*>(p))

// ---------------- packed f32x2 helpers (IEEE fp32 per lane) ----------------
typedef unsigned long long u64;
__device__ __forceinline__ u64 bc2(float v) {
    u64 r; asm("mov.b64 %0,{%1,%1};" : "=l"(r) : "f"(v)); return r;
}
__device__ __forceinline__ u64 fma2(u64 a, u64 b, u64 c) {
    u64 d; asm("fma.rn.f32x2 %0,%1,%2,%3;" : "=l"(d) : "l"(a),"l"(b),"l"(c)); return d;
}
__device__ __forceinline__ u64 mul2(u64 a, u64 b) {
    u64 d; asm("mul.rn.f32x2 %0,%1,%2;" : "=l"(d) : "l"(a),"l"(b)); return d;
}
__device__ __forceinline__ u64 add2(u64 a, u64 b) {
    u64 d; asm("add.rn.f32x2 %0,%1,%2;" : "=l"(d) : "l"(a),"l"(b)); return d;
}

// ---------------- per-(b,w,n) mean / rstd, sliding sums, chunked ----------------
// Split across 3 launches (ch_base) so k_winS is the 4th launch in the graph
// (the ncu capture slot).
__global__ void k_musig(const float* __restrict__ x, int ch_base) {
    int b  = blockIdx.x >> 3;
    int ch = ch_base + (blockIdx.x & 7);
    int n  = threadIdx.x;
    int w0 = ch * MCW, wend = min(w0 + MCW, NW);
    if (w0 >= NW) return;
    const float* xb = x + (size_t)b*TT*NN + n;
    float S = 0.f, Q = 0.f;
    int t0 = 2*w0;
    #pragma unroll
    for (int t = 0; t < 30; ++t) {
        float v = xb[(t0+t)*NN];
        S += v; Q += v*v;
    }
    for (int w = w0; w < wend; ++w) {
        if (w > w0) {
            int tp = 2*(w-1);
            float v0 = xb[tp*NN],      v1 = xb[(tp+1)*NN];
            float a0 = xb[(tp+30)*NN], a1 = xb[(tp+31)*NN];
            S += (a0 + a1) - (v0 + v1);
            Q += (a0*a0 + a1*a1) - (v0*v0 + v1*v1);
        }
        float mu  = S * (1.0f/30.0f);
        float var = (Q - S*S*(1.0f/30.0f)) * (1.0f/29.0f);
        float rs  = rsqrtf(fmaxf(var, 1e-8f));
        int idx = (b*NW + w)*NN + n;
        g_mu[idx]   = mu;
        g_rstd[idx] = rs;
    }
}

// ---------------- fused single pass: sliding Gram -> corr -> raw power sums ----------------
// 1n x 2m per thread (one packed u64 lane), 512-thread blocks covering a full
// 32x32 tile. Minimal register state: S=8 u64, G=1 u64 -> ~50 regs, so
// (512,2) = 32 warps/SM is structurally guaranteed (64-reg budget).
__global__ void __launch_bounds__(512, 2) k_winS(const float* __restrict__ x) {
    int blk  = blockIdx.x;
    int b    = blk / (10*NCH);
    int rest = blk % (10*NCH);
    int tile = rest / NCH;
    int ch   = rest % NCH;
    int tin = c_ti[tile], tjn = c_tj[tile];
    int tid = threadIdx.x;
    int n  = tin*32 + (tid >> 4);
    int m0 = tjn*32 + (tid & 15)*2;
    const float* xb = x + (size_t)b*TT*NN;
    int w0 = ch*CHW, wend = min(w0 + CHW, NW);

    // build Gram for the first window of the chunk
    u64 G = 0ull;
    {
        const float* p = xb + (2*w0)*NN;
        #pragma unroll
        for (int t = 0; t < 30; ++t) {
            G = fma2(bc2(p[n]), LDU(p + m0), G);
            p += NN;
        }
    }

    u64 S0=0ull,S1=0ull,S2=0ull,S3=0ull,S4=0ull,S5=0ull,S6=0ull,S7=0ull;

    const float* pmu = g_mu   + (b*NW + w0)*NN;
    const float* prs = g_rstd + (b*NW + w0)*NN;
    for (int w = w0; w < wend; ++w) {
        if (w > w0) {
            const float* p = xb + (2*w)*NN;
            G = fma2(bc2(-p[n - 2*NN]),  LDU(p + m0 - 2*NN),  G);
            G = fma2(bc2(-p[n - NN]),    LDU(p + m0 - NN),    G);
            G = fma2(bc2( p[n + 28*NN]), LDU(p + m0 + 28*NN), G);
            G = fma2(bc2( p[n + 29*NN]), LDU(p + m0 + 29*NN), G);
        }
        float mu_n = pmu[n];
        float rs_n = prs[n];
        u64 mum = LDU(pmu + m0);
        u64 rm  = LDU(prs + m0);
        u64 t  = fma2(bc2(-30.0f * mu_n), mum, G);     // G - 30*mu_n*mu_m
        u64 sr = mul2(bc2((1.0f/29.0f) * rs_n), rm);   // (rn/29)*rm
        u64 c  = mul2(t, sr);
        u64 c2 = mul2(c, c);
        u64 c3 = mul2(c2, c);
        u64 c4 = mul2(c2, c2);
        S0 = add2(S0, c);
        S1 = add2(S1, c2);
        S2 = add2(S2, c3);
        S3 = add2(S3, c4);
        S4 = fma2(c4, c,  S4);
        S5 = fma2(c4, c2, S5);
        S6 = fma2(c4, c3, S6);
        S7 = fma2(c4, c4, S7);
        pmu += NN; prs += NN;
    }

    const int D = NCH*BB*NN*NN;
    int base = ((ch*BB + b)*NN + n)*NN + m0;
    *reinterpret_cast<u64*>(&g_S[0*D + base]) = S0;
    *reinterpret_cast<u64*>(&g_S[1*D + base]) = S1;
    *reinterpret_cast<u64*>(&g_S[2*D + base]) = S2;
    *reinterpret_cast<u64*>(&g_S[3*D + base]) = S3;
    *reinterpret_cast<u64*>(&g_S[4*D + base]) = S4;
    *reinterpret_cast<u64*>(&g_S[5*D + base]) = S5;
    *reinterpret_cast<u64*>(&g_S[6*D + base]) = S6;
    *reinterpret_cast<u64*>(&g_S[7*D + base]) = S7;
}

// ---------------- reduce: power sums -> central moments (binomial, double) ----------------
__global__ void __launch_bounds__(256) k_redS() {
    int b    = blockIdx.x / 10;
    int tile = blockIdx.x % 10;
    int tin = c_ti[tile], tjn = c_tj[tile];
    int tid = threadIdx.x;
    int n  = tin*32 + (tid >> 3);
    int m0 = tjn*32 + (tid & 7)*4;
    const int D = NCH*BB*NN*NN;
    float A[8][4];
    #pragma unroll
    for (int p = 0; p < 8; ++p) { A[p][0]=0.f; A[p][1]=0.f; A[p][2]=0.f; A[p][3]=0.f; }
    #pragma unroll
    for (int ch = 0; ch < NCH; ++ch) {
        #pragma unroll
        for (int p = 0; p < 8; ++p) {
            float4 v = LD4(&g_S[p*D + ((ch*BB + b)*NN + n)*NN + m0]);
            A[p][0]+=v.x; A[p][1]+=v.y; A[p][2]+=v.z; A[p][3]+=v.w;
        }
    }
    const int DC = BB*NN*NN;
    const double invN = 1.0/498.0;
    #pragma unroll
    for (int j = 0; j < 4; ++j) {
        int m = m0 + j;
        double a1=A[0][j]*invN, a2=A[1][j]*invN, a3=A[2][j]*invN, a4=A[3][j]*invN;
        double a5=A[4][j]*invN, a6=A[5][j]*invN, a7=A[6][j]*invN, a8=A[7][j]*invN;
        double mm = a1;
        double m_2 = mm*mm, m_3 = m_2*mm, m_4 = m_2*m_2;
        double m_5 = m_4*mm, m_6 = m_4*m_2, m_8 = m_4*m_4;
        double M2 = a2 - m_2;
        double M4 = a4 - 4.0*mm*a3 + 6.0*m_2*a2 - 3.0*m_4;
        double M8 = a8 - 8.0*mm*a7 + 28.0*m_2*a6 - 56.0*m_3*a5 + 70.0*m_4*a4
                    - 56.0*m_5*a3 + 28.0*m_6*a2 - 7.0*m_8;
        float v2 = (float)M2, v4 = (float)M4, v8 = (float)M8;
        if (n == m) { v2 = 0.f; v4 = 0.f; v8 = 0.f; }   // diag corr == 1 exactly
        int idx = (b*NN + n)*NN + m;
        g_cm[idx] = v2; g_cm[DC + idx] = v4; g_cm[2*DC + idx] = v8;
        if (tin != tjn) {
            int tdx = (b*NN + m)*NN + n;
            g_cm[tdx] = v2; g_cm[DC + tdx] = v4; g_cm[2*DC + tdx] = v8;
        }
    }
}

// ---------------- row stats of cm (warp-per-row, shuffle reductions) ----------------
__global__ void k_rowstats() {
    int row  = blockIdx.x*4 + (threadIdx.x >> 5);   // (d*BB+b)*NN + n
    int lane = threadIdx.x & 31;
    float4 v = LD4(&g_cm[row*NN + lane*4]);
    float s = (v.x + v.y) + (v.z + v.w);
    #pragma unroll
    for (int o = 16; o > 0; o >>= 1) s += __shfl_xor_sync(0xffffffffu, s, o);
    float mean = s * (1.0f/128.0f);
    float c0 = v.x-mean, c1 = v.y-mean, c2 = v.z-mean, c3 = v.w-mean;
    float q = c0*c0 + c1*c1 + c2*c2 + c3*c3;
    #pragma unroll
    for (int o = 16; o > 0; o >>= 1) q += __shfl_xor_sync(0xffffffffu, q, o);
    if (lane == 0) {
        g_rmean[row] = mean;
        g_rinv[row]  = rsqrtf(fmaxf(q, 1e-8f));
    }
}

// ---------------- ho planes: per-d rowwise corr of cm_d -> g_S (reused scratch) ----------------
__global__ void __launch_bounds__(128) k_ho() {
    __shared__ float rowc[8][NN];
    __shared__ float rin[8];
    int d   = blockIdx.x >> 8;          // 0..2
    int rem = blockIdx.x & 255;
    int b   = rem >> 4;
    int n0  = (rem & 15) * 8;
    int t   = threadIdx.x;              // = m
    int base = (d*BB + b)*NN;
    #pragma unroll
    for (int r = 0; r < 8; ++r)
        rowc[r][t] = g_cm[(base + n0 + r)*NN + t] - g_rmean[base + n0 + r];
    if (t < 8) rin[t] = g_rinv[base + n0 + t];
    __syncthreads();

    int m = t;
    float rm_m = g_rmean[base + m];
    float ri_m = g_rinv [base + m];
    float acc[8] = {0,0,0,0,0,0,0,0};
    #pragma unroll 4
    for (int f = 0; f < NN; ++f) {
        float col = g_cm[(base + f)*NN + m] - rm_m;   // cm symmetric
        #pragma unroll
        for (int r = 0; r < 8; ++r) acc[r] += rowc[r][f]*col;
    }
    float* hoP = g_S;   // dead scratch after k_redS
    #pragma unroll
    for (int r = 0; r < 8; ++r) {
        float corr = acc[r] * rin[r] * ri_m;
        if (n0 + r == m) corr = 1.0f;
        hoP[(size_t)d*BB*NN*NN + (b*NN + n0 + r)*NN + m] = corr;
    }
}

// ---------------- A = mean of 3 ho planes; dis = rsqrt(rowsum(A)+1) ----------------
__global__ void k_Adis() {
    __shared__ float red[4];
    int row = blockIdx.x;               // b*NN + n
    int t = threadIdx.x;                // = m
    const float* hoP = g_S;
    const size_t DC = (size_t)BB*NN*NN;
    float v = (hoP[row*NN + t] + hoP[DC + row*NN + t] + hoP[2*DC + row*NN + t]) * (1.0f/3.0f);
    g_A[row*NN + t] = v;
    float s = v;
    #pragma unroll
    for (int o = 16; o > 0; o >>= 1) s += __shfl_xor_sync(0xffffffffu, s, o);
    if ((t & 31) == 0) red[t >> 5] = s;
    __syncthreads();
    if (t == 0) {
        float tot = red[0] + red[1] + red[2] + red[3];
        g_dis[row] = rsqrtf(fmaxf(tot + 1.0f, 1e-8f));
    }
}

// ---------------- X = layernorm(concat(cm2,cm4,cm8)) ----------------
__global__ void k_ln(const float* __restrict__ gam, const float* __restrict__ bet) {
    __shared__ float red[NN];
    int b = blockIdx.x / NN, n = blockIdx.x % NN, t = threadIdx.x;
    float v[3];
    #pragma unroll
    for (int d = 0; d < 3; ++d) v[d] = g_cm[((d*BB+b)*NN + n)*NN + t];
    red[t] = v[0] + v[1] + v[2]; __syncthreads();
    for (int s = 64; s > 0; s >>= 1) { if (t < s) red[t] += red[t+s]; __syncthreads(); }
    float mean = red[0] * (1.0f/384.0f);
    __syncthreads();
    float q = 0.f;
    #pragma unroll
    for (int d = 0; d < 3; ++d) { float c = v[d]-mean; q += c*c; }
    red[t] = q; __syncthreads();
    for (int s = 64; s > 0; s >>= 1) { if (t < s) red[t] += red[t+s]; __syncthreads(); }
    float rs = rsqrtf(red[0]*(1.0f/384.0f) + 1e-5f);
    #pragma unroll
    for (int d = 0; d < 3; ++d) {
        int f = d*NN + t;
        g_X[(b*NN + n)*IND + f] = (v[d]-mean)*rs*gam[f] + bet[f];
    }
}

// ---------------- generic small SGEMM: C = In@W + bias ----------------
__device__ __forceinline__ void gemm_body(const float* __restrict__ In,
                                          const float* __restrict__ W,
                                          const float* __restrict__ bias,
                                          float* __restrict__ C, int K) {
    __shared__ float As[32][33];
    __shared__ float Bs[32][33];
    int tx = threadIdx.x, ty = threadIdx.y;
    int tid = ty*16 + tx;
    int row0 = blockIdx.y*32, col0 = blockIdx.x*32;
    float a00=0.f, a01=0.f, a10=0.f, a11=0.f;
    for (int k0 = 0; k0 < K; k0 += 32) {
        #pragma unroll
        for (int l = 0; l < 4; ++l) {
            int e = tid + l*256; int i = e>>5, j = e&31;
            As[i][j] = In[(row0+i)*K + k0 + j];
            Bs[i][j] = W [(k0+i)*DM + col0 + j];
        }
        __syncthreads();
        #pragma unroll
        for (int kk = 0; kk < 32; ++kk) {
            float x0 = As[ty*2][kk],   x1 = As[ty*2+1][kk];
            float w0 = Bs[kk][tx*2],   w1 = Bs[kk][tx*2+1];
            a00 += x0*w0; a01 += x0*w1; a10 += x1*w0; a11 += x1*w1;
        }
        __syncthreads();
    }
    int r = row0 + ty*2, c = col0 + tx*2;
    C[r*DM + c]       = a00 + bias[c];
    C[r*DM + c + 1]   = a01 + bias[c+1];
    C[(r+1)*DM + c]   = a10 + bias[c];
    C[(r+1)*DM + c+1] = a11 + bias[c+1];
}
__global__ void k_gemm1(const float* __restrict__ W, const float* __restrict__ b) {
    gemm_body(g_X, W, b, g_P, IND);
}
__global__ void k_gemm2(const float* __restrict__ W, const float* __restrict__ b) {
    gemm_body(g_H, W, b, g_P2, DM);
}

// ---------------- Out = relu(A_norm @ P), A_norm built on the fly ----------------
__device__ __forceinline__ void amul_body(const float* __restrict__ P,
                                          float* __restrict__ O) {
    __shared__ float As[32][32];
    __shared__ float Ps[32][64];
    int blk = blockIdx.x;
    int b = blk / 16, rest = blk % 16;
    int n0 = (rest / 4)*32, c0 = (rest % 4)*64;
    int tid = threadIdx.x;
    int tx = tid & 63, ty = tid >> 6;
    float acc[8] = {0,0,0,0,0,0,0,0};
    const float* Ab = g_A   + b*NN*NN;
    const float* db = g_dis + b*NN;
    for (int k0 = 0; k0 < NN; k0 += 32) {
        #pragma unroll
        for (int l = 0; l < 4; ++l) {
            int e = tid + l*256; int i = e>>5, j = e&31;
            float v = Ab[(n0+i)*NN + k0 + j];
            if (n0+i == k0+j) v += 1.0f;               // A_hat = A + I
            As[i][j] = v * db[n0+i] * db[k0+j];
        }
        #pragma unroll
        for (int l = 0; l < 8; ++l) {
            int e = tid + l*256; int j = e>>6, c = e&63;
            Ps[j][c] = P[(b*NN + k0 + j)*DM + c0 + c];
        }
        __syncthreads();
        #pragma unroll
        for (int j = 0; j < 32; ++j) {
            float pv = Ps[j][tx];
            #pragma unroll
            for (int r = 0; r < 8; ++r) acc[r] += As[ty + 4*r][j] * pv;
        }
        __syncthreads();
    }
    #pragma unroll
    for (int r = 0; r < 8; ++r)
        O[(b*NN + n0 + ty + 4*r)*DM + c0 + tx] = fmaxf(acc[r], 0.0f);
}
__global__ void k_amul1() { amul_body(g_P,  g_H);  }
__global__ void k_amul2() { amul_body(g_P2, g_H2); }

// ---------------- final pool + sigmoid ----------------
__global__ void k_final(const float* __restrict__ Wc, const float* __restrict__ bc,
                        float* __restrict__ out) {
    __shared__ float red[DM];
    int b = blockIdx.x, t = threadIdx.x;
    float s = 0.f;
    #pragma unroll 4
    for (int nn = 0; nn < NN; ++nn) s += g_H2[(b*NN + nn)*DM + t];
    float g = s * (1.0f/128.0f);
    red[t] = g * Wc[t];
    __syncthreads();
    for (int st = 128; st > 0; st >>= 1) { if (t < st) red[t] += red[t+st]; __syncthreads(); }
    if (t == 0) {
        float v = red[0] + bc[0];
        out[b] = 1.0f / (1.0f + expf(-v));
    }
}

// ---------------- launch ----------------
extern "C" void kernel_launch(void* const* d_in, const int* in_sizes, int n_in,
                              void* d_out, int out_size) {
    const float* x   = (const float*)d_in[0];
    const float* gam = (const float*)d_in[1];
    const float* bet = (const float*)d_in[2];
    const float* W1  = (const float*)d_in[3];
    const float* b1  = (const float*)d_in[4];
    const float* W2  = (const float*)d_in[5];
    const float* b2  = (const float*)d_in[6];
    const float* Wc  = (const float*)d_in[7];
    const float* bc  = (const float*)d_in[8];
    float* out = (float*)d_out;

    // musig split into 3 launches so k_winS is the 4th launch (ncu capture slot)
    k_musig   <<<BB*8, 128>>>(x, 0);
    k_musig   <<<BB*8, 128>>>(x, 8);
    k_musig   <<<BB*8, 128>>>(x, 16);
    k_winS    <<<BB*10*NCH, 512>>>(x);
    k_redS    <<<BB*10, 256>>>();
    k_rowstats<<<3*BB*NN/4, 128>>>();
    k_ho      <<<3*BB*16, 128>>>();
    k_Adis    <<<BB*NN, 128>>>();
    k_ln      <<<BB*NN, 128>>>(gam, bet);
    k_gemm1   <<<dim3(DM/32, BB*NN/32), dim3(16,16)>>>(W1, b1);
    k_amul1   <<<BB*16, 256>>>();
    k_gemm2   <<<dim3(DM/32, BB*NN/32), dim3(16,16)>>>(W2, b2);
    k_amul2   <<<BB*16, 256>>>();
    k_final   <<<BB, DM>>>(Wc, bc, out);
}

// round 12
// speedup vs baseline: 1.0851x; 1.0851x over previous
#include <cuda_runtime.h>
#include <math.h>

#define BB   16
#define TT   1024
#define NN   128
#define NW   498
#define DM   256
#define IND  384
#define NCH  8       // window chunks (64 windows each, last=50)
#define CHW  64
#define MCH  24      // window chunks for musig
#define MCW  21

// ---------------- scratch (static device globals; no allocation) ----------------
__device__ __align__(16) float2 g_ps[BB*NW*NN];  // per (b,w,n): (p, s) with s=rstd/sqrt(29), p=sqrt(30)*mu*s
__device__ float g_S   [8*NCH*BB*NN*NN];    // per-chunk partial power sums S1..S8 (later reused for ho planes)
__device__ float g_cm  [3*BB*NN*NN];        // central moments d=2,4,8 (full, diag=0)
__device__ float g_rmean[3*BB*NN];
__device__ float g_rinv [3*BB*NN];
__device__ float g_A  [BB*NN*NN];           // averaged ho (diag=1)
__device__ float g_dis[BB*NN];              // rsqrt(rowsum(A)+1)
__device__ float g_X  [BB*NN*IND];          // layernormed features
__device__ float g_P  [BB*NN*DM];
__device__ float g_H  [BB*NN*DM];
__device__ float g_P2 [BB*NN*DM];
__device__ float g_H2 [BB*NN*DM];

__device__ const int c_ti[10] = {0,0,0,0,1,1,1,2,2,3};
__device__ const int c_tj[10] = {0,1,2,3,1,2,3,2,3,3};

#define LD4(p) (*reinterpret_cast<const float4*>(p))
#define LDU(p) (*reinterpret_cast<const unsigned long long*>(p))

// ---------------- packed f32x2 helpers (IEEE fp32 per lane) ----------------
typedef unsigned long long u64;
__device__ __forceinline__ u64 bc2(float v) {
    u64 r; asm("mov.b64 %0,{%1,%1};" : "=l"(r) : "f"(v)); return r;
}
__device__ __forceinline__ u64 pk2(float a, float b) {
    u64 r; asm("mov.b64 %0,{%1,%2};" : "=l"(r) : "f"(a),"f"(b)); return r;
}
__device__ __forceinline__ u64 fma2(u64 a, u64 b, u64 c) {
    u64 d; asm("fma.rn.f32x2 %0,%1,%2,%3;" : "=l"(d) : "l"(a),"l"(b),"l"(c)); return d;
}
__device__ __forceinline__ u64 mul2(u64 a, u64 b) {
    u64 d; asm("mul.rn.f32x2 %0,%1,%2;" : "=l"(d) : "l"(a),"l"(b)); return d;
}
__device__ __forceinline__ u64 add2(u64 a, u64 b) {
    u64 d; asm("add.rn.f32x2 %0,%1,%2;" : "=l"(d) : "l"(a),"l"(b)); return d;
}

// ---------------- per-(b,w,n) scaled stats (p,s), sliding sums, chunked ----------------
// Split across 3 launches (ch_base) so k_winS is the 4th launch in the graph
// (the ncu capture slot).
__global__ void k_musig(const float* __restrict__ x, int ch_base) {
    int b  = blockIdx.x >> 3;
    int ch = ch_base + (blockIdx.x & 7);
    int n  = threadIdx.x;
    int w0 = ch * MCW, wend = min(w0 + MCW, NW);
    if (w0 >= NW) return;
    const float* xb = x + (size_t)b*TT*NN + n;
    float S = 0.f, Q = 0.f;
    int t0 = 2*w0;
    #pragma unroll
    for (int t = 0; t < 30; ++t) {
        float v = xb[(t0+t)*NN];
        S += v; Q += v*v;
    }
    for (int w = w0; w < wend; ++w) {
        if (w > w0) {
            int tp = 2*(w-1);
            float v0 = xb[tp*NN],      v1 = xb[(tp+1)*NN];
            float a0 = xb[(tp+30)*NN], a1 = xb[(tp+31)*NN];
            S += (a0 + a1) - (v0 + v1);
            Q += (a0*a0 + a1*a1) - (v0*v0 + v1*v1);
        }
        float mu  = S * (1.0f/30.0f);
        float var = (Q - S*S*(1.0f/30.0f)) * (1.0f/29.0f);
        float rs  = rsqrtf(fmaxf(var, 1e-8f));
        float s   = rs * 0.18569534f;          // rstd / sqrt(29)
        float p   = mu * s * 5.4772256f;       // sqrt(30) * mu * s
        g_ps[(b*NW + w)*NN + n] = make_float2(p, s);
    }
}

// ---------------- fused single pass: sliding Gram -> corr -> raw power sums ----------------
// 1n x 2m per thread (one packed u64 lane), 512-thread blocks, full 32x32 tile.
// n-side x rows staged in smem as adjacent-row pairs (float2); per-window stats
// come from the interleaved g_ps array (1 LDG.128 m-side + 1 LDG.64 n-side).
__global__ void __launch_bounds__(512, 2) k_winS(const float* __restrict__ x) {
    __shared__ float2 s_xn2[78][32];    // (x[2t'], x[2t'+1]) for the tile's n-columns
    int blk  = blockIdx.x;
    int b    = blk / (10*NCH);
    int rest = blk % (10*NCH);
    int tile = rest / NCH;
    int ch   = rest % NCH;
    int tin = c_ti[tile], tjn = c_tj[tile];
    int tid = threadIdx.x;
    int nloc = tid >> 4;
    int n  = tin*32 + nloc;
    int m0 = tjn*32 + (tid & 15)*2;
    const float* xb = x + (size_t)b*TT*NN;
    int w0 = ch*CHW, wend = min(w0 + CHW, NW);

    // stage n-column row-pairs for this chunk
    {
        int ncol0 = tin*32;
        for (int idx = tid; idx < 78*32; idx += 512) {
            int lp = idx >> 5, nl = idx & 31;
            int t2a = w0 + lp;
            if (t2a < 512) {
                float a = xb[(2*t2a)*NN   + ncol0 + nl];
                float c = xb[(2*t2a+1)*NN + ncol0 + nl];
                s_xn2[lp][nl] = make_float2(a, c);
            }
        }
    }
    __syncthreads();

    // build Gram for the first window of the chunk (15 row-pairs)
    u64 G = 0ull;
    {
        const float* p = xb + (2*w0)*NN;
        #pragma unroll
        for (int t2 = 0; t2 < 15; ++t2) {
            float2 xn = s_xn2[t2][nloc];
            G = fma2(bc2(xn.x), LDU(p + m0),      G);
            G = fma2(bc2(xn.y), LDU(p + m0 + NN), G);
            p += 2*NN;
        }
    }

    u64 S0=0ull,S1=0ull,S2=0ull,S3=0ull,S4=0ull,S5=0ull,S6=0ull,S7=0ull;

    const float2* pps = g_ps + (size_t)(b*NW + w0)*NN;
    for (int w = w0; w < wend; ++w) {
        if (w > w0) {
            int wl = w - w0;
            float2 xt = s_xn2[wl-1][nloc];     // rows 2w-2, 2w-1
            float2 xl = s_xn2[wl+14][nloc];    // rows 2w+28, 2w+29
            const float* p = xb + (2*w)*NN;
            G = fma2(bc2(-xt.x), LDU(p + m0 - 2*NN),  G);
            G = fma2(bc2(-xt.y), LDU(p + m0 - NN),    G);
            G = fma2(bc2( xl.x), LDU(p + m0 + 28*NN), G);
            G = fma2(bc2( xl.y), LDU(p + m0 + 29*NN), G);
        }
        float4 m4 = *reinterpret_cast<const float4*>(pps + m0);  // (p0,s0,p1,s1)
        float2 n2 = pps[n];                                      // (pn,sn)
        u64 pm2 = pk2(m4.x, m4.z);
        u64 sm2 = pk2(m4.y, m4.w);
        // c = G*sn*sm - pn*pm
        u64 c  = fma2(bc2(-n2.x), pm2, mul2(mul2(bc2(n2.y), sm2), G));
        u64 c2 = mul2(c, c);
        u64 c3 = mul2(c2, c);
        u64 c4 = mul2(c2, c2);
        S0 = add2(S0, c);
        S1 = add2(S1, c2);
        S2 = add2(S2, c3);
        S3 = add2(S3, c4);
        S4 = fma2(c4, c,  S4);
        S5 = fma2(c4, c2, S5);
        S6 = fma2(c4, c3, S6);
        S7 = fma2(c4, c4, S7);
        pps += NN;
    }

    const int D = NCH*BB*NN*NN;
    int base = ((ch*BB + b)*NN + n)*NN + m0;
    *reinterpret_cast<u64*>(&g_S[0*D + base]) = S0;
    *reinterpret_cast<u64*>(&g_S[1*D + base]) = S1;
    *reinterpret_cast<u64*>(&g_S[2*D + base]) = S2;
    *reinterpret_cast<u64*>(&g_S[3*D + base]) = S3;
    *reinterpret_cast<u64*>(&g_S[4*D + base]) = S4;
    *reinterpret_cast<u64*>(&g_S[5*D + base]) = S5;
    *reinterpret_cast<u64*>(&g_S[6*D + base]) = S6;
    *reinterpret_cast<u64*>(&g_S[7*D + base]) = S7;
}

// ---------------- reduce: power sums -> central moments (binomial, double) ----------------
__global__ void __launch_bounds__(256) k_redS() {
    int b    = blockIdx.x / 10;
    int tile = blockIdx.x % 10;
    int tin = c_ti[tile], tjn = c_tj[tile];
    int tid = threadIdx.x;
    int n  = tin*32 + (tid >> 3);
    int m0 = tjn*32 + (tid & 7)*4;
    const int D = NCH*BB*NN*NN;
    float A[8][4];
    #pragma unroll
    for (int p = 0; p < 8; ++p) { A[p][0]=0.f; A[p][1]=0.f; A[p][2]=0.f; A[p][3]=0.f; }
    #pragma unroll
    for (int ch = 0; ch < NCH; ++ch) {
        #pragma unroll
        for (int p = 0; p < 8; ++p) {
            float4 v = LD4(&g_S[p*D + ((ch*BB + b)*NN + n)*NN + m0]);
            A[p][0]+=v.x; A[p][1]+=v.y; A[p][2]+=v.z; A[p][3]+=v.w;
        }
    }
    const int DC = BB*NN*NN;
    const double invN = 1.0/498.0;
    #pragma unroll
    for (int j = 0; j < 4; ++j) {
        int m = m0 + j;
        double a1=A[0][j]*invN, a2=A[1][j]*invN, a3=A[2][j]*invN, a4=A[3][j]*invN;
        double a5=A[4][j]*invN, a6=A[5][j]*invN, a7=A[6][j]*invN, a8=A[7][j]*invN;
        double mm = a1;
        double m_2 = mm*mm, m_3 = m_2*mm, m_4 = m_2*m_2;
        double m_5 = m_4*mm, m_6 = m_4*m_2, m_8 = m_4*m_4;
        double M2 = a2 - m_2;
        double M4 = a4 - 4.0*mm*a3 + 6.0*m_2*a2 - 3.0*m_4;
        double M8 = a8 - 8.0*mm*a7 + 28.0*m_2*a6 - 56.0*m_3*a5 + 70.0*m_4*a4
                    - 56.0*m_5*a3 + 28.0*m_6*a2 - 7.0*m_8;
        float v2 = (float)M2, v4 = (float)M4, v8 = (float)M8;
        if (n == m) { v2 = 0.f; v4 = 0.f; v8 = 0.f; }   // diag corr == 1 exactly
        int idx = (b*NN + n)*NN + m;
        g_cm[idx] = v2; g_cm[DC + idx] = v4; g_cm[2*DC + idx] = v8;
        if (tin != tjn) {
            int tdx = (b*NN + m)*NN + n;
            g_cm[tdx] = v2; g_cm[DC + tdx] = v4; g_cm[2*DC + tdx] = v8;
        }
    }
}

// ---------------- row stats of cm (warp-per-row, shuffle reductions) ----------------
__global__ void k_rowstats() {
    int row  = blockIdx.x*4 + (threadIdx.x >> 5);   // (d*BB+b)*NN + n
    int lane = threadIdx.x & 31;
    float4 v = LD4(&g_cm[row*NN + lane*4]);
    float s = (v.x + v.y) + (v.z + v.w);
    #pragma unroll
    for (int o = 16; o > 0; o >>= 1) s += __shfl_xor_sync(0xffffffffu, s, o);
    float mean = s * (1.0f/128.0f);
    float c0 = v.x-mean, c1 = v.y-mean, c2 = v.z-mean, c3 = v.w-mean;
    float q = c0*c0 + c1*c1 + c2*c2 + c3*c3;
    #pragma unroll
    for (int o = 16; o > 0; o >>= 1) q += __shfl_xor_sync(0xffffffffu, q, o);
    if (lane == 0) {
        g_rmean[row] = mean;
        g_rinv[row]  = rsqrtf(fmaxf(q, 1e-8f));
    }
}

// ---------------- ho planes: per-d rowwise corr of cm_d -> g_S (reused scratch) ----------------
__global__ void __launch_bounds__(128) k_ho() {
    __shared__ float rowc[8][NN];
    __shared__ float rin[8];
    int d   = blockIdx.x >> 8;          // 0..2
    int rem = blockIdx.x & 255;
    int b   = rem >> 4;
    int n0  = (rem & 15) * 8;
    int t   = threadIdx.x;              // = m
    int base = (d*BB + b)*NN;
    #pragma unroll
    for (int r = 0; r < 8; ++r)
        rowc[r][t] = g_cm[(base + n0 + r)*NN + t] - g_rmean[base + n0 + r];
    if (t < 8) rin[t] = g_rinv[base + n0 + t];
    __syncthreads();

    int m = t;
    float rm_m = g_rmean[base + m];
    float ri_m = g_rinv [base + m];
    float acc[8] = {0,0,0,0,0,0,0,0};
    #pragma unroll 4
    for (int f = 0; f < NN; ++f) {
        float col = g_cm[(base + f)*NN + m] - rm_m;   // cm symmetric
        #pragma unroll
        for (int r = 0; r < 8; ++r) acc[r] += rowc[r][f]*col;
    }
    float* hoP = g_S;   // dead scratch after k_redS
    #pragma unroll
    for (int r = 0; r < 8; ++r) {
        float corr = acc[r] * rin[r] * ri_m;
        if (n0 + r == m) corr = 1.0f;
        hoP[(size_t)d*BB*NN*NN + (b*NN + n0 + r)*NN + m] = corr;
    }
}

// ---------------- A = mean of 3 ho planes; dis = rsqrt(rowsum(A)+1) ----------------
__global__ void k_Adis() {
    __shared__ float red[4];
    int row = blockIdx.x;               // b*NN + n
    int t = threadIdx.x;                // = m
    const float* hoP = g_S;
    const size_t DC = (size_t)BB*NN*NN;
    float v = (hoP[row*NN + t] + hoP[DC + row*NN + t] + hoP[2*DC + row*NN + t]) * (1.0f/3.0f);
    g_A[row*NN + t] = v;
    float s = v;
    #pragma unroll
    for (int o = 16; o > 0; o >>= 1) s += __shfl_xor_sync(0xffffffffu, s, o);
    if ((t & 31) == 0) red[t >> 5] = s;
    __syncthreads();
    if (t == 0) {
        float tot = red[0] + red[1] + red[2] + red[3];
        g_dis[row] = rsqrtf(fmaxf(tot + 1.0f, 1e-8f));
    }
}

// ---------------- X = layernorm(concat(cm2,cm4,cm8)) ----------------
__global__ void k_ln(const float* __restrict__ gam, const float* __restrict__ bet) {
    __shared__ float red[NN];
    int b = blockIdx.x / NN, n = blockIdx.x % NN, t = threadIdx.x;
    float v[3];
    #pragma unroll
    for (int d = 0; d < 3; ++d) v[d] = g_cm[((d*BB+b)*NN + n)*NN + t];
    red[t] = v[0] + v[1] + v[2]; __syncthreads();
    for (int s = 64; s > 0; s >>= 1) { if (t < s) red[t] += red[t+s]; __syncthreads(); }
    float mean = red[0] * (1.0f/384.0f);
    __syncthreads();
    float q = 0.f;
    #pragma unroll
    for (int d = 0; d < 3; ++d) { float c = v[d]-mean; q += c*c; }
    red[t] = q; __syncthreads();
    for (int s = 64; s > 0; s >>= 1) { if (t < s) red[t] += red[t+s]; __syncthreads(); }
    float rs = rsqrtf(red[0]*(1.0f/384.0f) + 1e-5f);
    #pragma unroll
    for (int d = 0; d < 3; ++d) {
        int f = d*NN + t;
        g_X[(b*NN + n)*IND + f] = (v[d]-mean)*rs*gam[f] + bet[f];
    }
}

// ---------------- generic small SGEMM: C = In@W + bias ----------------
__device__ __forceinline__ void gemm_body(const float* __restrict__ In,
                                          const float* __restrict__ W,
                                          const float* __restrict__ bias,
                                          float* __restrict__ C, int K) {
    __shared__ float As[32][33];
    __shared__ float Bs[32][33];
    int tx = threadIdx.x, ty = threadIdx.y;
    int tid = ty*16 + tx;
    int row0 = blockIdx.y*32, col0 = blockIdx.x*32;
    float a00=0.f, a01=0.f, a10=0.f, a11=0.f;
    for (int k0 = 0; k0 < K; k0 += 32) {
        #pragma unroll
        for (int l = 0; l < 4; ++l) {
            int e = tid + l*256; int i = e>>5, j = e&31;
            As[i][j] = In[(row0+i)*K + k0 + j];
            Bs[i][j] = W [(k0+i)*DM + col0 + j];
        }
        __syncthreads();
        #pragma unroll
        for (int kk = 0; kk < 32; ++kk) {
            float x0 = As[ty*2][kk],   x1 = As[ty*2+1][kk];
            float w0 = Bs[kk][tx*2],   w1 = Bs[kk][tx*2+1];
            a00 += x0*w0; a01 += x0*w1; a10 += x1*w0; a11 += x1*w1;
        }
        __syncthreads();
    }
    int r = row0 + ty*2, c = col0 + tx*2;
    C[r*DM + c]       = a00 + bias[c];
    C[r*DM + c + 1]   = a01 + bias[c+1];
    C[(r+1)*DM + c]   = a10 + bias[c];
    C[(r+1)*DM + c+1] = a11 + bias[c+1];
}
__global__ void k_gemm1(const float* __restrict__ W, const float* __restrict__ b) {
    gemm_body(g_X, W, b, g_P, IND);
}
__global__ void k_gemm2(const float* __restrict__ W, const float* __restrict__ b) {
    gemm_body(g_H, W, b, g_P2, DM);
}

// ---------------- Out = relu(A_norm @ P), A_norm built on the fly ----------------
__device__ __forceinline__ void amul_body(const float* __restrict__ P,
                                          float* __restrict__ O) {
    __shared__ float As[32][32];
    __shared__ float Ps[32][64];
    int blk = blockIdx.x;
    int b = blk / 16, rest = blk % 16;
    int n0 = (rest / 4)*32, c0 = (rest % 4)*64;
    int tid = threadIdx.x;
    int tx = tid & 63, ty = tid >> 6;
    float acc[8] = {0,0,0,0,0,0,0,0};
    const float* Ab = g_A   + b*NN*NN;
    const float* db = g_dis + b*NN;
    for (int k0 = 0; k0 < NN; k0 += 32) {
        #pragma unroll
        for (int l = 0; l < 4; ++l) {
            int e = tid + l*256; int i = e>>5, j = e&31;
            float v = Ab[(n0+i)*NN + k0 + j];
            if (n0+i == k0+j) v += 1.0f;               // A_hat = A + I
            As[i][j] = v * db[n0+i] * db[k0+j];
        }
        #pragma unroll
        for (int l = 0; l < 8; ++l) {
            int e = tid + l*256; int j = e>>6, c = e&63;
            Ps[j][c] = P[(b*NN + k0 + j)*DM + c0 + c];
        }
        __syncthreads();
        #pragma unroll
        for (int j = 0; j < 32; ++j) {
            float pv = Ps[j][tx];
            #pragma unroll
            for (int r = 0; r < 8; ++r) acc[r] += As[ty + 4*r][j] * pv;
        }
        __syncthreads();
    }
    #pragma unroll
    for (int r = 0; r < 8; ++r)
        O[(b*NN + n0 + ty + 4*r)*DM + c0 + tx] = fmaxf(acc[r], 0.0f);
}
__global__ void k_amul1() { amul_body(g_P,  g_H);  }
__global__ void k_amul2() { amul_body(g_P2, g_H2); }

// ---------------- final pool + sigmoid ----------------
__global__ void k_final(const float* __restrict__ Wc, const float* __restrict__ bc,
                        float* __restrict__ out) {
    __shared__ float red[DM];
    int b = blockIdx.x, t = threadIdx.x;
    float s = 0.f;
    #pragma unroll 4
    for (int nn = 0; nn < NN; ++nn) s += g_H2[(b*NN + nn)*DM + t];
    float g = s * (1.0f/128.0f);
    red[t] = g * Wc[t];
    __syncthreads();
    for (int st = 128; st > 0; st >>= 1) { if (t < st) red[t] += red[t+st]; __syncthreads(); }
    if (t == 0) {
        float v = red[0] + bc[0];
        out[b] = 1.0f / (1.0f + expf(-v));
    }
}

// ---------------- launch ----------------
extern "C" void kernel_launch(void* const* d_in, const int* in_sizes, int n_in,
                              void* d_out, int out_size) {
    const float* x   = (const float*)d_in[0];
    const float* gam = (const float*)d_in[1];
    const float* bet = (const float*)d_in[2];
    const float* W1  = (const float*)d_in[3];
    const float* b1  = (const float*)d_in[4];
    const float* W2  = (const float*)d_in[5];
    const float* b2  = (const float*)d_in[6];
    const float* Wc  = (const float*)d_in[7];
    const float* bc  = (const float*)d_in[8];
    float* out = (float*)d_out;

    // musig split into 3 launches so k_winS is the 4th launch (ncu capture slot)
    k_musig   <<<BB*8, 128>>>(x, 0);
    k_musig   <<<BB*8, 128>>>(x, 8);
    k_musig   <<<BB*8, 128>>>(x, 16);
    k_winS    <<<BB*10*NCH, 512>>>(x);
    k_redS    <<<BB*10, 256>>>();
    k_rowstats<<<3*BB*NN/4, 128>>>();
    k_ho      <<<3*BB*16, 128>>>();
    k_Adis    <<<BB*NN, 128>>>();
    k_ln      <<<BB*NN, 128>>>(gam, bet);
    k_gemm1   <<<dim3(DM/32, BB*NN/32), dim3(16,16)>>>(W1, b1);
    k_amul1   <<<BB*16, 256>>>();
    k_gemm2   <<<dim3(DM/32, BB*NN/32), dim3(16,16)>>>(W2, b2);
    k_amul2   <<<BB*16, 256>>>();
    k_final   <<<BB, DM>>>(Wc, bc, out);
}

// round 14
// speedup vs baseline: 1.1312x; 1.0425x over previous
#include <cuda_runtime.h>
#include <math.h>

#define BB   16
#define TT   1024
#define NN   128
#define NW   498
#define DM   256
#define IND  384
#define NCH  8       // window chunks (64 windows each, last=50)
#define CHW  64
#define MCH  24      // window chunks for musig
#define MCW  21

// ---------------- scratch (static device globals; no allocation) ----------------
__device__ __align__(16) float2 g_ps[BB*NW*NN];  // per (b,w,n): (p, s) with s=rstd/sqrt(29), p=sqrt(30)*mu*s
__device__ float g_S   [8*NCH*BB*NN*NN];    // per-chunk partial power sums S1..S8 (later reused for ho planes)
__device__ float g_cm  [3*BB*NN*NN];        // central moments d=2,4,8 (full, diag=0)
__device__ float g_rmean[3*BB*NN];
__device__ float g_rinv [3*BB*NN];
__device__ float g_A  [BB*NN*NN];           // averaged ho (diag=1)
__device__ float g_dis[BB*NN];              // rsqrt(rowsum(A)+1)
__device__ float g_X  [BB*NN*IND];          // layernormed features
__device__ float g_P  [BB*NN*DM];
__device__ float g_H  [BB*NN*DM];
__device__ float g_P2 [BB*NN*DM];
__device__ float g_H2 [BB*NN*DM];

__device__ const int c_ti[10] = {0,0,0,0,1,1,1,2,2,3};
__device__ const int c_tj[10] = {0,1,2,3,1,2,3,2,3,3};

#define LD4(p) (*reinterpret_cast<const float4*>(p))
#define LDU(p) (*reinterpret_cast<const unsigned long long*>(p))

// ---------------- packed f32x2 helpers (IEEE fp32 per lane) ----------------
typedef unsigned long long u64;
__device__ __forceinline__ u64 bc2(float v) {
    u64 r; asm("mov.b64 %0,{%1,%1};" : "=l"(r) : "f"(v)); return r;
}
__device__ __forceinline__ u64 pk2(float a, float b) {
    u64 r; asm("mov.b64 %0,{%1,%2};" : "=l"(r) : "f"(a),"f"(b)); return r;
}
__device__ __forceinline__ u64 fma2(u64 a, u64 b, u64 c) {
    u64 d; asm("fma.rn.f32x2 %0,%1,%2,%3;" : "=l"(d) : "l"(a),"l"(b),"l"(c)); return d;
}
__device__ __forceinline__ u64 mul2(u64 a, u64 b) {
    u64 d; asm("mul.rn.f32x2 %0,%1,%2;" : "=l"(d) : "l"(a),"l"(b)); return d;
}
__device__ __forceinline__ u64 add2(u64 a, u64 b) {
    u64 d; asm("add.rn.f32x2 %0,%1,%2;" : "=l"(d) : "l"(a),"l"(b)); return d;
}

// ---------------- per-(b,w,n) scaled stats (p,s), sliding sums, chunked ----------------
// Split across 3 launches (ch_base) so k_winS is the 4th launch in the graph
// (the ncu capture slot).
__global__ void k_musig(const float* __restrict__ x, int ch_base) {
    int b  = blockIdx.x >> 3;
    int ch = ch_base + (blockIdx.x & 7);
    int n  = threadIdx.x;
    int w0 = ch * MCW, wend = min(w0 + MCW, NW);
    if (w0 >= NW) return;
    const float* xb = x + (size_t)b*TT*NN + n;
    float S = 0.f, Q = 0.f;
    int t0 = 2*w0;
    #pragma unroll
    for (int t = 0; t < 30; ++t) {
        float v = xb[(t0+t)*NN];
        S += v; Q += v*v;
    }
    for (int w = w0; w < wend; ++w) {
        if (w > w0) {
            int tp = 2*(w-1);
            float v0 = xb[tp*NN],      v1 = xb[(tp+1)*NN];
            float a0 = xb[(tp+30)*NN], a1 = xb[(tp+31)*NN];
            S += (a0 + a1) - (v0 + v1);
            Q += (a0*a0 + a1*a1) - (v0*v0 + v1*v1);
        }
        float mu  = S * (1.0f/30.0f);
        float var = (Q - S*S*(1.0f/30.0f)) * (1.0f/29.0f);
        float rs  = rsqrtf(fmaxf(var, 1e-8f));
        float s   = rs * 0.18569534f;          // rstd / sqrt(29)
        float p   = mu * s * 5.4772256f;       // sqrt(30) * mu * s
        g_ps[(b*NW + w)*NN + n] = make_float2(p, s);
    }
}

// ---------------- fused single pass: sliding Gram -> corr -> raw power sums ----------------
// 1n x 2m per thread (one packed u64 lane), 512-thread blocks, full 32x32 tile.
// Branch-free slide loop with running pointers (alu trim vs R12).
__global__ void __launch_bounds__(512, 2) k_winS(const float* __restrict__ x) {
    __shared__ float2 s_xn2[78][32];    // (x[2t'], x[2t'+1]) for the tile's n-columns
    int blk  = blockIdx.x;
    int b    = blk / (10*NCH);
    int rest = blk % (10*NCH);
    int tile = rest / NCH;
    int ch   = rest % NCH;
    int tin = c_ti[tile], tjn = c_tj[tile];
    int tid = threadIdx.x;
    int nloc = tid >> 4;
    int n  = tin*32 + nloc;
    int m0 = tjn*32 + (tid & 15)*2;
    const float* xb = x + (size_t)b*TT*NN;
    int w0 = ch*CHW, wend = min(w0 + CHW, NW);

    // stage n-column row-pairs for this chunk
    {
        int ncol0 = tin*32;
        for (int idx = tid; idx < 78*32; idx += 512) {
            int lp = idx >> 5, nl = idx & 31;
            int t2a = w0 + lp;
            if (t2a < 512) {
                float a = xb[(2*t2a)*NN   + ncol0 + nl];
                float c = xb[(2*t2a+1)*NN + ncol0 + nl];
                s_xn2[lp][nl] = make_float2(a, c);
            }
        }
    }
    __syncthreads();

    // build Gram for the first window of the chunk (15 row-pairs)
    u64 G = 0ull;
    {
        const float* p = xb + (2*w0)*NN;
        #pragma unroll
        for (int t2 = 0; t2 < 15; ++t2) {
            float2 xn = s_xn2[t2][nloc];
            G = fma2(bc2(xn.x), LDU(p + m0),      G);
            G = fma2(bc2(xn.y), LDU(p + m0 + NN), G);
            p += 2*NN;
        }
    }

    u64 S0=0ull,S1=0ull,S2=0ull,S3=0ull,S4=0ull,S5=0ull,S6=0ull,S7=0ull;

    const float2* pps = g_ps + (size_t)(b*NW + w0)*NN;

    #define WSTATS() do { \
        float4 m4 = *reinterpret_cast<const float4*>(pps + m0); \
        float2 n2 = pps[n]; \
        u64 pm2 = pk2(m4.x, m4.z); \
        u64 sm2 = pk2(m4.y, m4.w); \
        u64 c  = fma2(bc2(-n2.x), pm2, mul2(mul2(bc2(n2.y), sm2), G)); \
        u64 c2 = mul2(c, c); \
        u64 c3 = mul2(c2, c); \
        u64 c4 = mul2(c2, c2); \
        S0 = add2(S0, c);  S1 = add2(S1, c2); \
        S2 = add2(S2, c3); S3 = add2(S3, c4); \
        S4 = fma2(c4, c,  S4); S5 = fma2(c4, c2, S5); \
        S6 = fma2(c4, c3, S6); S7 = fma2(c4, c4, S7); \
    } while (0)

    // first window (no slide)
    WSTATS();
    pps += NN;

    // branch-free slide loop with running pointers
    const float2* pxt = &s_xn2[0][nloc];    // rows 2w-2, 2w-1
    const float2* pxl = &s_xn2[15][nloc];   // rows 2w+28, 2w+29
    const float*  pm  = xb + (size_t)2*(w0+1)*NN + m0;
    for (int w = w0+1; w < wend; ++w) {
        float2 xt = *pxt; pxt += 32;
        float2 xl = *pxl; pxl += 32;
        G = fma2(bc2(-xt.x), LDU(pm - 2*NN),  G);
        G = fma2(bc2(-xt.y), LDU(pm - NN),    G);
        G = fma2(bc2( xl.x), LDU(pm + 28*NN), G);
        G = fma2(bc2( xl.y), LDU(pm + 29*NN), G);
        WSTATS();
        pps += NN; pm += 2*NN;
    }
    #undef WSTATS

    const int D = NCH*BB*NN*NN;
    int base = ((ch*BB + b)*NN + n)*NN + m0;
    *reinterpret_cast<u64*>(&g_S[0*D + base]) = S0;
    *reinterpret_cast<u64*>(&g_S[1*D + base]) = S1;
    *reinterpret_cast<u64*>(&g_S[2*D + base]) = S2;
    *reinterpret_cast<u64*>(&g_S[3*D + base]) = S3;
    *reinterpret_cast<u64*>(&g_S[4*D + base]) = S4;
    *reinterpret_cast<u64*>(&g_S[5*D + base]) = S5;
    *reinterpret_cast<u64*>(&g_S[6*D + base]) = S6;
    *reinterpret_cast<u64*>(&g_S[7*D + base]) = S7;
}

// ---------------- reduce: power sums -> central moments (binomial, double) ----------------
__global__ void __launch_bounds__(256) k_redS() {
    int b    = blockIdx.x / 10;
    int tile = blockIdx.x % 10;
    int tin = c_ti[tile], tjn = c_tj[tile];
    int tid = threadIdx.x;
    int n  = tin*32 + (tid >> 3);
    int m0 = tjn*32 + (tid & 7)*4;
    const int D = NCH*BB*NN*NN;
    float A[8][4];
    #pragma unroll
    for (int p = 0; p < 8; ++p) { A[p][0]=0.f; A[p][1]=0.f; A[p][2]=0.f; A[p][3]=0.f; }
    #pragma unroll
    for (int ch = 0; ch < NCH; ++ch) {
        #pragma unroll
        for (int p = 0; p < 8; ++p) {
            float4 v = LD4(&g_S[p*D + ((ch*BB + b)*NN + n)*NN + m0]);
            A[p][0]+=v.x; A[p][1]+=v.y; A[p][2]+=v.z; A[p][3]+=v.w;
        }
    }
    const int DC = BB*NN*NN;
    const double invN = 1.0/498.0;
    #pragma unroll
    for (int j = 0; j < 4; ++j) {
        int m = m0 + j;
        double a1=A[0][j]*invN, a2=A[1][j]*invN, a3=A[2][j]*invN, a4=A[3][j]*invN;
        double a5=A[4][j]*invN, a6=A[5][j]*invN, a7=A[6][j]*invN, a8=A[7][j]*invN;
        double mm = a1;
        double m_2 = mm*mm, m_3 = m_2*mm, m_4 = m_2*m_2;
        double m_5 = m_4*mm, m_6 = m_4*m_2, m_8 = m_4*m_4;
        double M2 = a2 - m_2;
        double M4 = a4 - 4.0*mm*a3 + 6.0*m_2*a2 - 3.0*m_4;
        double M8 = a8 - 8.0*mm*a7 + 28.0*m_2*a6 - 56.0*m_3*a5 + 70.0*m_4*a4
                    - 56.0*m_5*a3 + 28.0*m_6*a2 - 7.0*m_8;
        float v2 = (float)M2, v4 = (float)M4, v8 = (float)M8;
        if (n == m) { v2 = 0.f; v4 = 0.f; v8 = 0.f; }   // diag corr == 1 exactly
        int idx = (b*NN + n)*NN + m;
        g_cm[idx] = v2; g_cm[DC + idx] = v4; g_cm[2*DC + idx] = v8;
        if (tin != tjn) {
            int tdx = (b*NN + m)*NN + n;
            g_cm[tdx] = v2; g_cm[DC + tdx] = v4; g_cm[2*DC + tdx] = v8;
        }
    }
}

// ---------------- row stats of cm (warp-per-row, shuffle reductions) ----------------
__global__ void k_rowstats() {
    int row  = blockIdx.x*4 + (threadIdx.x >> 5);   // (d*BB+b)*NN + n
    int lane = threadIdx.x & 31;
    float4 v = LD4(&g_cm[row*NN + lane*4]);
    float s = (v.x + v.y) + (v.z + v.w);
    #pragma unroll
    for (int o = 16; o > 0; o >>= 1) s += __shfl_xor_sync(0xffffffffu, s, o);
    float mean = s * (1.0f/128.0f);
    float c0 = v.x-mean, c1 = v.y-mean, c2 = v.z-mean, c3 = v.w-mean;
    float q = c0*c0 + c1*c1 + c2*c2 + c3*c3;
    #pragma unroll
    for (int o = 16; o > 0; o >>= 1) q += __shfl_xor_sync(0xffffffffu, q, o);
    if (lane == 0) {
        g_rmean[row] = mean;
        g_rinv[row]  = rsqrtf(fmaxf(q, 1e-8f));
    }
}

// ---------------- ho planes: per-d rowwise corr of cm_d -> g_S (reused scratch) ----------------
__global__ void __launch_bounds__(128) k_ho() {
    __shared__ float rowc[8][NN];
    __shared__ float rin[8];
    int d   = blockIdx.x >> 8;          // 0..2
    int rem = blockIdx.x & 255;
    int b   = rem >> 4;
    int n0  = (rem & 15) * 8;
    int t   = threadIdx.x;              // = m
    int base = (d*BB + b)*NN;
    #pragma unroll
    for (int r = 0; r < 8; ++r)
        rowc[r][t] = g_cm[(base + n0 + r)*NN + t] - g_rmean[base + n0 + r];
    if (t < 8) rin[t] = g_rinv[base + n0 + t];
    __syncthreads();

    int m = t;
    float rm_m = g_rmean[base + m];
    float ri_m = g_rinv [base + m];
    float acc[8] = {0,0,0,0,0,0,0,0};
    #pragma unroll 8
    for (int f = 0; f < NN; ++f) {
        float col = g_cm[(base + f)*NN + m] - rm_m;   // cm symmetric
        #pragma unroll
        for (int r = 0; r < 8; ++r) acc[r] += rowc[r][f]*col;
    }
    float* hoP = g_S;   // dead scratch after k_redS
    #pragma unroll
    for (int r = 0; r < 8; ++r) {
        float corr = acc[r] * rin[r] * ri_m;
        if (n0 + r == m) corr = 1.0f;
        hoP[(size_t)d*BB*NN*NN + (b*NN + n0 + r)*NN + m] = corr;
    }
}

// ---------------- A = mean of 3 ho planes; dis = rsqrt(rowsum(A)+1) ----------------
__global__ void k_Adis() {
    __shared__ float red[4];
    int row = blockIdx.x;               // b*NN + n
    int t = threadIdx.x;                // = m
    const float* hoP = g_S;
    const size_t DC = (size_t)BB*NN*NN;
    float v = (hoP[row*NN + t] + hoP[DC + row*NN + t] + hoP[2*DC + row*NN + t]) * (1.0f/3.0f);
    g_A[row*NN + t] = v;
    float s = v;
    #pragma unroll
    for (int o = 16; o > 0; o >>= 1) s += __shfl_xor_sync(0xffffffffu, s, o);
    if ((t & 31) == 0) red[t >> 5] = s;
    __syncthreads();
    if (t == 0) {
        float tot = red[0] + red[1] + red[2] + red[3];
        g_dis[row] = rsqrtf(fmaxf(tot + 1.0f, 1e-8f));
    }
}

// ---------------- X = layernorm(concat(cm2,cm4,cm8)) ----------------
__global__ void k_ln(const float* __restrict__ gam, const float* __restrict__ bet) {
    __shared__ float red[NN];
    int b = blockIdx.x / NN, n = blockIdx.x % NN, t = threadIdx.x;
    float v[3];
    #pragma unroll
    for (int d = 0; d < 3; ++d) v[d] = g_cm[((d*BB+b)*NN + n)*NN + t];
    red[t] = v[0] + v[1] + v[2]; __syncthreads();
    for (int s = 64; s > 0; s >>= 1) { if (t < s) red[t] += red[t+s]; __syncthreads(); }
    float mean = red[0] * (1.0f/384.0f);
    __syncthreads();
    float q = 0.f;
    #pragma unroll
    for (int d = 0; d < 3; ++d) { float c = v[d]-mean; q += c*c; }
    red[t] = q; __syncthreads();
    for (int s = 64; s > 0; s >>= 1) { if (t < s) red[t] += red[t+s]; __syncthreads(); }
    float rs = rsqrtf(red[0]*(1.0f/384.0f) + 1e-5f);
    #pragma unroll
    for (int d = 0; d < 3; ++d) {
        int f = d*NN + t;
        g_X[(b*NN + n)*IND + f] = (v[d]-mean)*rs*gam[f] + bet[f];
    }
}

// ---------------- 64x64 SGEMM, 4x4 register blocking: C = In@W + bias ----------------
__device__ __forceinline__ void gemm64(const float* __restrict__ In,
                                       const float* __restrict__ W,
                                       const float* __restrict__ bias,
                                       float* __restrict__ C, int K) {
    __shared__ float As[16][68];   // transposed: As[kk][row]
    __shared__ float Bs[16][68];
    int tid = threadIdx.x;         // 256
    int tx = tid & 15, ty = tid >> 4;
    int row0 = blockIdx.y*64, col0 = blockIdx.x*64;
    float acc[4][4] = {{0}};
    int lr = tid >> 2, lk = (tid & 3)*4;       // A-load: row lr, k-quad lk
    int bk = tid >> 4, bcq = (tid & 15)*4;     // B-load: k-row bk, col-quad bcq
    for (int k0 = 0; k0 < K; k0 += 16) {
        float4 av = LD4(&In[(size_t)(row0+lr)*K + k0 + lk]);
        As[lk+0][lr]=av.x; As[lk+1][lr]=av.y; As[lk+2][lr]=av.z; As[lk+3][lr]=av.w;
        float4 wv = LD4(&W[(size_t)(k0+bk)*DM + col0 + bcq]);
        *reinterpret_cast<float4*>(&Bs[bk][bcq]) = wv;
        __syncthreads();
        #pragma unroll
        for (int kk = 0; kk < 16; ++kk) {
            float4 a = *reinterpret_cast<const float4*>(&As[kk][ty*4]);
            float4 bv = *reinterpret_cast<const float4*>(&Bs[kk][tx*4]);
            acc[0][0] += a.x*bv.x; acc[0][1] += a.x*bv.y; acc[0][2] += a.x*bv.z; acc[0][3] += a.x*bv.w;
            acc[1][0] += a.y*bv.x; acc[1][1] += a.y*bv.y; acc[1][2] += a.y*bv.z; acc[1][3] += a.y*bv.w;
            acc[2][0] += a.z*bv.x; acc[2][1] += a.z*bv.y; acc[2][2] += a.z*bv.z; acc[2][3] += a.z*bv.w;
            acc[3][0] += a.w*bv.x; acc[3][1] += a.w*bv.y; acc[3][2] += a.w*bv.z; acc[3][3] += a.w*bv.w;
        }
        __syncthreads();
    }
    float4 bb = LD4(&bias[col0 + tx*4]);
    #pragma unroll
    for (int i = 0; i < 4; ++i) {
        float4 o;
        o.x = acc[i][0] + bb.x; o.y = acc[i][1] + bb.y;
        o.z = acc[i][2] + bb.z; o.w = acc[i][3] + bb.w;
        *reinterpret_cast<float4*>(&C[(size_t)(row0 + ty*4 + i)*DM + col0 + tx*4]) = o;
    }
}
__global__ void __launch_bounds__(256) k_gemm1(const float* __restrict__ W, const float* __restrict__ b) {
    gemm64(g_X, W, b, g_P, IND);
}
__global__ void __launch_bounds__(256) k_gemm2(const float* __restrict__ W, const float* __restrict__ b) {
    gemm64(g_H, W, b, g_P2, DM);
}

// ---------------- Out = relu(A_norm @ P), A_norm built on the fly ----------------
__device__ __forceinline__ void amul_body(const float* __restrict__ P,
                                          float* __restrict__ O) {
    __shared__ float As[32][32];
    __shared__ float Ps[32][64];
    int blk = blockIdx.x;
    int b = blk / 16, rest = blk % 16;
    int n0 = (rest / 4)*32, c0 = (rest % 4)*64;
    int tid = threadIdx.x;
    int tx = tid & 63, ty = tid >> 6;
    float acc[8] = {0,0,0,0,0,0,0,0};
    const float* Ab = g_A   + b*NN*NN;
    const float* db = g_dis + b*NN;
    for (int k0 = 0; k0 < NN; k0 += 32) {
        #pragma unroll
        for (int l = 0; l < 4; ++l) {
            int e = tid + l*256; int i = e>>5, j = e&31;
            float v = Ab[(n0+i)*NN + k0 + j];
            if (n0+i == k0+j) v += 1.0f;               // A_hat = A + I
            As[i][j] = v * db[n0+i] * db[k0+j];
        }
        #pragma unroll
        for (int l = 0; l < 8; ++l) {
            int e = tid + l*256; int j = e>>6, c = e&63;
            Ps[j][c] = P[(b*NN + k0 + j)*DM + c0 + c];
        }
        __syncthreads();
        #pragma unroll
        for (int j = 0; j < 32; ++j) {
            float pv = Ps[j][tx];
            #pragma unroll
            for (int r = 0; r < 8; ++r) acc[r] += As[ty + 4*r][j] * pv;
        }
        __syncthreads();
    }
    #pragma unroll
    for (int r = 0; r < 8; ++r)
        O[(b*NN + n0 + ty + 4*r)*DM + c0 + tx] = fmaxf(acc[r], 0.0f);
}
__global__ void k_amul1() { amul_body(g_P,  g_H);  }
__global__ void k_amul2() { amul_body(g_P2, g_H2); }

// ---------------- final pool + sigmoid ----------------
__global__ void k_final(const float* __restrict__ Wc, const float* __restrict__ bc,
                        float* __restrict__ out) {
    __shared__ float red[DM];
    int b = blockIdx.x, t = threadIdx.x;
    float s = 0.f;
    #pragma unroll 4
    for (int nn = 0; nn < NN; ++nn) s += g_H2[(b*NN + nn)*DM + t];
    float g = s * (1.0f/128.0f);
    red[t] = g * Wc[t];
    __syncthreads();
    for (int st = 128; st > 0; st >>= 1) { if (t < st) red[t] += red[t+st]; __syncthreads(); }
    if (t == 0) {
        float v = red[0] + bc[0];
        out[b] = 1.0f / (1.0f + expf(-v));
    }
}

// ---------------- launch ----------------
extern "C" void kernel_launch(void* const* d_in, const int* in_sizes, int n_in,
                              void* d_out, int out_size) {
    const float* x   = (const float*)d_in[0];
    const float* gam = (const float*)d_in[1];
    const float* bet = (const float*)d_in[2];
    const float* W1  = (const float*)d_in[3];
    const float* b1  = (const float*)d_in[4];
    const float* W2  = (const float*)d_in[5];
    const float* b2  = (const float*)d_in[6];
    const float* Wc  = (const float*)d_in[7];
    const float* bc  = (const float*)d_in[8];
    float* out = (float*)d_out;

    // musig split into 3 launches so k_winS is the 4th launch (ncu capture slot)
    k_musig   <<<BB*8, 128>>>(x, 0);
    k_musig   <<<BB*8, 128>>>(x, 8);
    k_musig   <<<BB*8, 128>>>(x, 16);
    k_winS    <<<BB*10*NCH, 512>>>(x);
    k_redS    <<<BB*10, 256>>>();
    k_rowstats<<<3*BB*NN/4, 128>>>();
    k_ho      <<<3*BB*16, 128>>>();
    k_Adis    <<<BB*NN, 128>>>();
    k_ln      <<<BB*NN, 128>>>(gam, bet);
    k_gemm1   <<<dim3(DM/64, BB*NN/64), 256>>>(W1, b1);
    k_amul1   <<<BB*16, 256>>>();
    k_gemm2   <<<dim3(DM/64, BB*NN/64), 256>>>(W2, b2);
    k_amul2   <<<BB*16, 256>>>();
    k_final   <<<BB, DM>>>(Wc, bc, out);
}